// round 3
// baseline (speedup 1.0000x reference)
#include <cuda_runtime.h>
#include <math.h>

#define NN 50000
#define EE 400000
#define FF 128
#define HH 8
#define CC 64
#define BB 64
#define KK 10
#define HC (HH*CC)     /* 512 */
#define ETOT (EE+NN)   /* 450000 edges incl. self loops */

// ---------------- scratch (device globals; no allocation allowed) ----------------
__device__ __align__(16) float g_h1[(size_t)NN*HC];    // x@W1
__device__ __align__(16) float g_out1[(size_t)NN*HC];  // elu(gat1)
__device__ __align__(16) float g_h2[(size_t)NN*CC];    // out1@W2
__device__ __align__(16) float g_out2[(size_t)NN*CC];  // elu(gat2)
__device__ __align__(16) float g_as1[NN*HH];
__device__ __align__(16) float g_ad1[NN*HH];
__device__ __align__(16) float g_as2[NN];
__device__ __align__(16) float g_ad2[NN];
__device__ __align__(16) float g_pooled[BB*CC];
__device__ int g_deg[NN];
__device__ int g_rowptr[NN+1];
__device__ int g_fill[NN];
__device__ int g_csr[ETOT];

// ---------------- CSR build ----------------
__global__ void k_init() {
    int i = blockIdx.x*blockDim.x + threadIdx.x;
    if (i < NN) { g_deg[i] = 1; g_fill[i] = 0; }   // deg starts at 1: self loop
    if (i < BB*CC) g_pooled[i] = 0.f;
}

__global__ void k_count(const int* __restrict__ dst) {
    int i = blockIdx.x*blockDim.x + threadIdx.x;
    if (i < EE) atomicAdd(&g_deg[dst[i]], 1);
}

// exclusive scan of g_deg[0..NN) -> g_rowptr, single block of 1024 threads
__global__ void k_scan() {
    __shared__ int sh[1024];
    int t = threadIdx.x;
    const int chunk = (NN + 1023) / 1024;  // 49
    int beg = t * chunk;
    int end = beg + chunk; if (end > NN) end = NN;
    int sum = 0;
    for (int i = beg; i < end; i++) sum += g_deg[i];
    sh[t] = sum;
    __syncthreads();
    for (int off = 1; off < 1024; off <<= 1) {
        int v = (t >= off) ? sh[t - off] : 0;
        __syncthreads();
        sh[t] += v;
        __syncthreads();
    }
    int run = (t == 0) ? 0 : sh[t - 1];
    for (int i = beg; i < end; i++) { g_rowptr[i] = run; run += g_deg[i]; }
    if (t == 1023) g_rowptr[NN] = sh[1023];
}

__global__ void k_scatter(const int* __restrict__ src, const int* __restrict__ dst) {
    int i = blockIdx.x*blockDim.x + threadIdx.x;
    if (i >= ETOT) return;
    int d, s;
    if (i < EE) { d = dst[i]; s = src[i]; }
    else        { d = i - EE; s = d; }          // self loop
    int pos = g_rowptr[d] + atomicAdd(&g_fill[d], 1);
    g_csr[pos] = s;
}

// ---------------- SGEMM: C[M,N] = A[M,K] @ B[K,N], K % 8 == 0 ----------------
__global__ void __launch_bounds__(256) k_sgemm(const float* __restrict__ A,
                                               const float* __restrict__ B,
                                               float* __restrict__ C,
                                               int M, int N, int K) {
    __shared__ float As[8][128];
    __shared__ float Bs[8][128];
    const int bm = blockIdx.y * 128, bn = blockIdx.x * 128;
    const int tid = threadIdx.x;
    const int tx = tid & 15, ty = tid >> 4;

    float acc[8][8];
    #pragma unroll
    for (int i = 0; i < 8; i++)
        #pragma unroll
        for (int j = 0; j < 8; j++) acc[i][j] = 0.f;

    for (int k0 = 0; k0 < K; k0 += 8) {
        // A tile: 128 rows x 8 k, one float4 per thread, stored transposed
        {
            int r  = tid >> 1;
            int c4 = (tid & 1) * 4;
            int row = bm + r;
            float4 av = make_float4(0.f, 0.f, 0.f, 0.f);
            if (row < M)
                av = *reinterpret_cast<const float4*>(A + (size_t)row * K + k0 + c4);
            As[c4+0][r] = av.x; As[c4+1][r] = av.y;
            As[c4+2][r] = av.z; As[c4+3][r] = av.w;
        }
        // B tile: 8 k x 128 cols, fully coalesced
        #pragma unroll
        for (int i = 0; i < 4; i++) {
            int lin = tid + i * 256;
            int kk = lin >> 7, cc = lin & 127;
            int col = bn + cc;
            Bs[kk][cc] = (col < N) ? B[(size_t)(k0 + kk) * N + col] : 0.f;
        }
        __syncthreads();
        #pragma unroll
        for (int k = 0; k < 8; k++) {
            float4 a0 = *reinterpret_cast<const float4*>(&As[k][ty*8]);
            float4 a1 = *reinterpret_cast<const float4*>(&As[k][ty*8+4]);
            float4 b0 = *reinterpret_cast<const float4*>(&Bs[k][tx*8]);
            float4 b1 = *reinterpret_cast<const float4*>(&Bs[k][tx*8+4]);
            float a[8] = {a0.x,a0.y,a0.z,a0.w,a1.x,a1.y,a1.z,a1.w};
            float b[8] = {b0.x,b0.y,b0.z,b0.w,b1.x,b1.y,b1.z,b1.w};
            #pragma unroll
            for (int i = 0; i < 8; i++)
                #pragma unroll
                for (int j = 0; j < 8; j++)
                    acc[i][j] += a[i] * b[j];
        }
        __syncthreads();
    }
    #pragma unroll
    for (int i = 0; i < 8; i++) {
        int row = bm + ty*8 + i;
        if (row >= M) continue;
        #pragma unroll
        for (int j = 0; j < 8; j++) {
            int col = bn + tx*8 + j;
            if (col < N) C[(size_t)row * N + col] = acc[i][j];
        }
    }
}

// ---------------- attention scores: a_s/a_d[n,h] = <h[n,h,:], att[h,:]> ----------------
__global__ void k_attn(const float* __restrict__ h,
                       const float* __restrict__ asrc,
                       const float* __restrict__ adst,
                       float* __restrict__ a_s, float* __restrict__ a_d,
                       int Hn, int NH) {
    int w = (blockIdx.x * blockDim.x + threadIdx.x) >> 5;
    if (w >= NH) return;
    int lane = threadIdx.x & 31;
    int head = w % Hn;
    const float* hp = h + (size_t)w * CC;
    float v0 = hp[lane], v1 = hp[lane + 32];
    float ps = v0 * __ldg(&asrc[head*CC + lane]) + v1 * __ldg(&asrc[head*CC + lane + 32]);
    float pd = v0 * __ldg(&adst[head*CC + lane]) + v1 * __ldg(&adst[head*CC + lane + 32]);
    #pragma unroll
    for (int o = 16; o; o >>= 1) {
        ps += __shfl_down_sync(0xffffffffu, ps, o);
        pd += __shfl_down_sync(0xffffffffu, pd, o);
    }
    if (lane == 0) { a_s[w] = ps; a_d[w] = pd; }
}

// ---------------- GAT aggregation: warp per (node, head), segment softmax + gather ----------------
__global__ void k_agg(const float* __restrict__ h,
                      const float* __restrict__ a_s,
                      const float* __restrict__ a_d,
                      const float* __restrict__ bias,
                      float* __restrict__ out,
                      int Hn, int NH) {
    int w = (blockIdx.x * blockDim.x + threadIdx.x) >> 5;
    if (w >= NH) return;
    int lane = threadIdx.x & 31;
    int n = w / Hn, head = w % Hn;
    int beg = g_rowptr[n], end = g_rowptr[n + 1];
    float adn = a_d[w];

    // pass 1: segment max (lane-parallel over edges)
    float m = -1e30f;
    for (int j = beg + lane; j < end; j += 32) {
        int s = g_csr[j];
        float e = a_s[s * Hn + head] + adn;
        e = e > 0.f ? e : 0.2f * e;
        m = fmaxf(m, e);
    }
    #pragma unroll
    for (int o = 16; o; o >>= 1) m = fmaxf(m, __shfl_xor_sync(0xffffffffu, m, o));

    // pass 2: denom
    float ssum = 0.f;
    for (int j = beg + lane; j < end; j += 32) {
        int s = g_csr[j];
        float e = a_s[s * Hn + head] + adn;
        e = e > 0.f ? e : 0.2f * e;
        ssum += __expf(e - m);
    }
    #pragma unroll
    for (int o = 16; o; o >>= 1) ssum += __shfl_xor_sync(0xffffffffu, ssum, o);
    float inv = 1.f / (ssum + 1e-16f);

    // pass 3: weighted gather (all lanes walk edges; lane = channel)
    float acc0 = 0.f, acc1 = 0.f;
    for (int j = beg; j < end; ++j) {
        int s = g_csr[j];
        float e = a_s[s * Hn + head] + adn;
        e = e > 0.f ? e : 0.2f * e;
        float alpha = __expf(e - m) * inv;
        const float* hp = h + ((size_t)s * Hn + head) * CC;
        acc0 += alpha * hp[lane];
        acc1 += alpha * hp[lane + 32];
    }
    float o0 = acc0 + bias[head*CC + lane];
    float o1 = acc1 + bias[head*CC + lane + 32];
    o0 = o0 > 0.f ? o0 : expm1f(o0);   // fused ELU
    o1 = o1 > 0.f ? o1 : expm1f(o1);
    out[(size_t)w * CC + lane]      = o0;
    out[(size_t)w * CC + lane + 32] = o1;
}

// ---------------- global add pool (batch is sorted) ----------------
__global__ void k_pool(const int* __restrict__ batch) {
    int c = threadIdx.x;             // 64 channels
    int n0 = blockIdx.x * 128;
    int n1 = n0 + 128; if (n1 > NN) n1 = NN;
    if (n0 >= NN) return;
    float acc = 0.f;
    int cur = batch[n0];
    for (int i = n0; i < n1; i++) {
        int b = batch[i];
        if (b != cur) { atomicAdd(&g_pooled[cur*CC + c], acc); acc = 0.f; cur = b; }
        acc += g_out2[(size_t)i * CC + c];
    }
    atomicAdd(&g_pooled[cur*CC + c], acc);
}

// ---------------- head MLP + log_softmax, one block of 64 per graph ----------------
__global__ void k_head(const float* __restrict__ w1, const float* __restrict__ b1v,
                       const float* __restrict__ w2, const float* __restrict__ b2v,
                       float* __restrict__ out) {
    __shared__ float p[64], zs[64], lg[KK];
    int b = blockIdx.x, t = threadIdx.x;
    p[t] = g_pooled[b*CC + t];
    __syncthreads();
    float z = b1v[t];
    #pragma unroll 16
    for (int k = 0; k < 64; k++) z += p[k] * w1[k*64 + t];
    z = z > 0.f ? z : expm1f(z);
    zs[t] = z;
    __syncthreads();
    if (t < KK) {
        float l = b2v[t];
        #pragma unroll 16
        for (int k = 0; k < 64; k++) l += zs[k] * w2[k*KK + t];
        lg[t] = l;
    }
    __syncthreads();
    if (t < KK) {
        float m = -1e30f;
        #pragma unroll
        for (int k = 0; k < KK; k++) m = fmaxf(m, lg[k]);
        float s = 0.f;
        #pragma unroll
        for (int k = 0; k < KK; k++) s += expf(lg[k] - m);
        out[b*KK + t] = lg[t] - m - logf(s);
    }
}

// ---------------- launch ----------------
extern "C" void kernel_launch(void* const* d_in, const int* in_sizes, int n_in,
                              void* d_out, int out_size) {
    const float* x        = (const float*)d_in[0];
    const int*   ei       = (const int*)  d_in[1];
    const int*   batch    = (const int*)  d_in[2];
    const float* W1       = (const float*)d_in[3];
    const float* att_src1 = (const float*)d_in[4];
    const float* att_dst1 = (const float*)d_in[5];
    const float* b1       = (const float*)d_in[6];
    const float* W2       = (const float*)d_in[7];
    const float* att_src2 = (const float*)d_in[8];
    const float* att_dst2 = (const float*)d_in[9];
    const float* b2       = (const float*)d_in[10];
    const float* l1w      = (const float*)d_in[11];
    const float* l1b      = (const float*)d_in[12];
    const float* l2w      = (const float*)d_in[13];
    const float* l2b      = (const float*)d_in[14];
    float* out = (float*)d_out;

    const int* src = ei;
    const int* dst = ei + EE;

    void *p_h1, *p_out1, *p_h2, *p_out2, *p_as1, *p_ad1, *p_as2, *p_ad2;
    cudaGetSymbolAddress(&p_h1,  g_h1);
    cudaGetSymbolAddress(&p_out1, g_out1);
    cudaGetSymbolAddress(&p_h2,  g_h2);
    cudaGetSymbolAddress(&p_out2, g_out2);
    cudaGetSymbolAddress(&p_as1, g_as1);
    cudaGetSymbolAddress(&p_ad1, g_ad1);
    cudaGetSymbolAddress(&p_as2, g_as2);
    cudaGetSymbolAddress(&p_ad2, g_ad2);
    float* h1   = (float*)p_h1;
    float* out1 = (float*)p_out1;
    float* h2   = (float*)p_h2;
    float* out2 = (float*)p_out2;
    float* as1  = (float*)p_as1;
    float* ad1  = (float*)p_ad1;
    float* as2  = (float*)p_as2;
    float* ad2  = (float*)p_ad2;

    // CSR build (by destination)
    k_init<<<(NN + 255)/256, 256>>>();
    k_count<<<(EE + 255)/256, 256>>>(dst);
    k_scan<<<1, 1024>>>();
    k_scatter<<<(ETOT + 255)/256, 256>>>(src, dst);

    // Layer 1: h1 = x @ W1  [50000,128]@[128,512]
    k_sgemm<<<dim3(HC/128, (NN + 127)/128), 256>>>(x, W1, h1, NN, HC, FF);
    k_attn<<<(NN*HH + 7)/8, 256>>>(h1, att_src1, att_dst1, as1, ad1, HH, NN*HH);
    k_agg <<<(NN*HH + 7)/8, 256>>>(h1, as1, ad1, b1, out1, HH, NN*HH);

    // Layer 2: h2 = out1 @ W2  [50000,512]@[512,64]
    k_sgemm<<<dim3((CC + 127)/128, (NN + 127)/128), 256>>>(out1, W2, h2, NN, CC, HC);
    k_attn<<<(NN + 7)/8, 256>>>(h2, att_src2, att_dst2, as2, ad2, 1, NN);
    k_agg <<<(NN + 7)/8, 256>>>(h2, as2, ad2, b2, out2, 1, NN);

    // Pool + head
    k_pool<<<(NN + 127)/128, 64>>>(batch);
    k_head<<<BB, 64>>>(l1w, l1b, l2w, l2b, out);
}

// round 5
// speedup vs baseline: 1.1953x; 1.1953x over previous
#include <cuda_runtime.h>
#include <math.h>

#define NN 50000
#define EE 400000
#define FF 128
#define HH 8
#define CC 64
#define BB 64
#define KK 10
#define HC (HH*CC)     /* 512 */
#define ETOT (EE+NN)   /* 450000 edges incl. self loops */

// ---------------- scratch (device globals; no allocation allowed) ----------------
__device__ __align__(16) float g_h1[(size_t)NN*HC];    // x@W1
__device__ __align__(16) float g_out1[(size_t)NN*HC];  // elu(gat1)
__device__ __align__(16) float g_h2[(size_t)NN*CC];    // out1@W2
__device__ __align__(16) float g_out2[(size_t)NN*CC];  // elu(gat2)
__device__ __align__(16) float g_as1[NN*HH];
__device__ __align__(16) float g_ad1[NN*HH];
__device__ __align__(16) float g_as2[NN];
__device__ __align__(16) float g_ad2[NN];
__device__ __align__(16) float g_pooled[BB*CC];
__device__ int g_deg[NN];
__device__ int g_rowptr[NN+1];
__device__ int g_fill[NN];
__device__ int g_csr[ETOT];

// ---------------- CSR build ----------------
__global__ void k_init() {
    int i = blockIdx.x*blockDim.x + threadIdx.x;
    if (i < NN) { g_deg[i] = 1; g_fill[i] = 0; }   // deg starts at 1: self loop
    if (i < BB*CC) g_pooled[i] = 0.f;
}

__global__ void k_count(const int* __restrict__ dst) {
    int i = blockIdx.x*blockDim.x + threadIdx.x;
    if (i < EE) atomicAdd(&g_deg[dst[i]], 1);
}

// exclusive scan of g_deg[0..NN) -> g_rowptr, single block of 1024 threads
__global__ void k_scan() {
    __shared__ int sh[1024];
    int t = threadIdx.x;
    const int chunk = (NN + 1023) / 1024;  // 49
    int beg = t * chunk;
    int end = beg + chunk; if (end > NN) end = NN;
    int sum = 0;
    for (int i = beg; i < end; i++) sum += g_deg[i];
    sh[t] = sum;
    __syncthreads();
    for (int off = 1; off < 1024; off <<= 1) {
        int v = (t >= off) ? sh[t - off] : 0;
        __syncthreads();
        sh[t] += v;
        __syncthreads();
    }
    int run = (t == 0) ? 0 : sh[t - 1];
    for (int i = beg; i < end; i++) { g_rowptr[i] = run; run += g_deg[i]; }
    if (t == 1023) g_rowptr[NN] = sh[1023];
}

__global__ void k_scatter(const int* __restrict__ src, const int* __restrict__ dst) {
    int i = blockIdx.x*blockDim.x + threadIdx.x;
    if (i >= ETOT) return;
    int d, s;
    if (i < EE) { d = dst[i]; s = src[i]; }
    else        { d = i - EE; s = d; }          // self loop
    int pos = g_rowptr[d] + atomicAdd(&g_fill[d], 1);
    g_csr[pos] = s;
}

// ---------------- SGEMM: C[M,N] = A[M,K] @ B[K,N] ----------------
// Double-buffered smem, register-prefetch pipeline. Requires:
//   K % BK == 0, N % BN == 0 (grid exact in N), 256 threads.
// Thread fragment cols split as {g*(BN/2) + tx*4 .. +3} for conflict-free LDS.128.
template<int BM,int BN,int BK,int TM,int TN>
__global__ void __launch_bounds__(256)
k_sgemm_t(const float* __restrict__ A, const float* __restrict__ B,
          float* __restrict__ C, int M, int N, int K)
{
    constexpr int THREADS = (BM/TM)*(BN/TN);        // must be 256
    constexpr int AF4 = BM*BK/(4*THREADS);          // float4 A loads / thread
    constexpr int BF4 = BK*BN/(4*THREADS);          // float4 B loads / thread
    constexpr int AR  = BK/4;                       // float4 per A gmem row chunk
    constexpr int BR  = BN/4;                       // float4 per B gmem row chunk
    constexpr int GM  = TM/4;                       // row groups of 4
    constexpr int GN  = TN/4;                       // col groups of 4

    __shared__ float As[2][BK][BM];
    __shared__ float Bs[2][BK][BN];

    const int bm = blockIdx.y*BM, bn = blockIdx.x*BN;
    const int tid = threadIdx.x;
    const int tx  = tid % (BN/TN);
    const int ty  = tid / (BN/TN);

    float4 ra[AF4], rb[BF4];

    const int nt = K/BK;

    // ---- load tile `t` (k-offset) into registers ----
    auto ldg = [&](int k0) {
        #pragma unroll
        for (int i = 0; i < AF4; i++) {
            int idx = tid + i*THREADS;
            int r = idx / AR, c4 = (idx % AR)*4;
            int row = bm + r;
            ra[i] = (row < M) ? *(const float4*)(A + (size_t)row*K + k0 + c4)
                              : make_float4(0.f,0.f,0.f,0.f);
        }
        #pragma unroll
        for (int i = 0; i < BF4; i++) {
            int idx = tid + i*THREADS;
            int kk = idx / BR, c4 = (idx % BR)*4;
            rb[i] = *(const float4*)(B + (size_t)(k0+kk)*N + bn + c4);
        }
    };
    // ---- store registers into smem buffer ----
    auto sts = [&](int buf) {
        #pragma unroll
        for (int i = 0; i < AF4; i++) {
            int idx = tid + i*THREADS;
            int r = idx / AR, c4 = (idx % AR)*4;
            As[buf][c4+0][r] = ra[i].x; As[buf][c4+1][r] = ra[i].y;
            As[buf][c4+2][r] = ra[i].z; As[buf][c4+3][r] = ra[i].w;
        }
        #pragma unroll
        for (int i = 0; i < BF4; i++) {
            int idx = tid + i*THREADS;
            int kk = idx / BR, c4 = (idx % BR)*4;
            *(float4*)&Bs[buf][kk][c4] = rb[i];
        }
    };

    float acc[TM][TN];
    #pragma unroll
    for (int i = 0; i < TM; i++)
        #pragma unroll
        for (int j = 0; j < TN; j++) acc[i][j] = 0.f;

    ldg(0);
    sts(0);
    __syncthreads();

    for (int t = 0; t < nt; t++) {
        int buf = t & 1;
        if (t + 1 < nt) ldg((t+1)*BK);        // LDGs in flight during compute
        #pragma unroll
        for (int k = 0; k < BK; k++) {
            float a[TM], b[TN];
            #pragma unroll
            for (int g = 0; g < GM; g++) {
                float4 v = *(const float4*)&As[buf][k][g*(BM/2) + ty*4];
                a[g*4+0]=v.x; a[g*4+1]=v.y; a[g*4+2]=v.z; a[g*4+3]=v.w;
            }
            #pragma unroll
            for (int g = 0; g < GN; g++) {
                float4 v = *(const float4*)&Bs[buf][k][g*(BN/2) + tx*4];
                b[g*4+0]=v.x; b[g*4+1]=v.y; b[g*4+2]=v.z; b[g*4+3]=v.w;
            }
            #pragma unroll
            for (int i = 0; i < TM; i++)
                #pragma unroll
                for (int j = 0; j < TN; j++)
                    acc[i][j] += a[i] * b[j];
        }
        if (t + 1 < nt) sts(buf ^ 1);
        __syncthreads();
    }

    // ---- epilogue: float4 stores, row-guarded (cols always exact) ----
    #pragma unroll
    for (int g = 0; g < GM; g++) {
        #pragma unroll
        for (int i = 0; i < 4; i++) {
            int row = bm + g*(BM/2) + ty*4 + i;
            if (row >= M) continue;
            #pragma unroll
            for (int h = 0; h < GN; h++) {
                float4 v = make_float4(acc[g*4+i][h*4+0], acc[g*4+i][h*4+1],
                                       acc[g*4+i][h*4+2], acc[g*4+i][h*4+3]);
                *(float4*)(C + (size_t)row*N + bn + h*(BN/2) + tx*4) = v;
            }
        }
    }
}

// ---------------- attention scores: a_s/a_d[n,h] = <h[n,h,:], att[h,:]> ----------------
__global__ void k_attn(const float* __restrict__ h,
                       const float* __restrict__ asrc,
                       const float* __restrict__ adst,
                       float* __restrict__ a_s, float* __restrict__ a_d,
                       int Hn, int NH) {
    int w = (blockIdx.x * blockDim.x + threadIdx.x) >> 5;
    if (w >= NH) return;
    int lane = threadIdx.x & 31;
    int head = w % Hn;
    const float* hp = h + (size_t)w * CC;
    float v0 = hp[lane], v1 = hp[lane + 32];
    float ps = v0 * __ldg(&asrc[head*CC + lane]) + v1 * __ldg(&asrc[head*CC + lane + 32]);
    float pd = v0 * __ldg(&adst[head*CC + lane]) + v1 * __ldg(&adst[head*CC + lane + 32]);
    #pragma unroll
    for (int o = 16; o; o >>= 1) {
        ps += __shfl_down_sync(0xffffffffu, ps, o);
        pd += __shfl_down_sync(0xffffffffu, pd, o);
    }
    if (lane == 0) { a_s[w] = ps; a_d[w] = pd; }
}

// ---------------- GAT aggregation: warp per (node, head), segment softmax + gather ----------------
__global__ void k_agg(const float* __restrict__ h,
                      const float* __restrict__ a_s,
                      const float* __restrict__ a_d,
                      const float* __restrict__ bias,
                      float* __restrict__ out,
                      int Hn, int NH) {
    int w = (blockIdx.x * blockDim.x + threadIdx.x) >> 5;
    if (w >= NH) return;
    int lane = threadIdx.x & 31;
    int n = w / Hn, head = w % Hn;
    int beg = g_rowptr[n], end = g_rowptr[n + 1];
    float adn = a_d[w];

    // pass 1: segment max (lane-parallel over edges)
    float m = -1e30f;
    for (int j = beg + lane; j < end; j += 32) {
        int s = g_csr[j];
        float e = a_s[s * Hn + head] + adn;
        e = e > 0.f ? e : 0.2f * e;
        m = fmaxf(m, e);
    }
    #pragma unroll
    for (int o = 16; o; o >>= 1) m = fmaxf(m, __shfl_xor_sync(0xffffffffu, m, o));

    // pass 2: denom
    float ssum = 0.f;
    for (int j = beg + lane; j < end; j += 32) {
        int s = g_csr[j];
        float e = a_s[s * Hn + head] + adn;
        e = e > 0.f ? e : 0.2f * e;
        ssum += __expf(e - m);
    }
    #pragma unroll
    for (int o = 16; o; o >>= 1) ssum += __shfl_xor_sync(0xffffffffu, ssum, o);
    float inv = 1.f / (ssum + 1e-16f);

    // pass 3: weighted gather (all lanes walk edges; lane = channel)
    float acc0 = 0.f, acc1 = 0.f;
    for (int j = beg; j < end; ++j) {
        int s = g_csr[j];
        float e = a_s[s * Hn + head] + adn;
        e = e > 0.f ? e : 0.2f * e;
        float alpha = __expf(e - m) * inv;
        const float* hp = h + ((size_t)s * Hn + head) * CC;
        acc0 += alpha * hp[lane];
        acc1 += alpha * hp[lane + 32];
    }
    float o0 = acc0 + bias[head*CC + lane];
    float o1 = acc1 + bias[head*CC + lane + 32];
    o0 = o0 > 0.f ? o0 : expm1f(o0);   // fused ELU
    o1 = o1 > 0.f ? o1 : expm1f(o1);
    out[(size_t)w * CC + lane]      = o0;
    out[(size_t)w * CC + lane + 32] = o1;
}

// ---------------- global add pool (batch is sorted) ----------------
__global__ void k_pool(const int* __restrict__ batch) {
    int c = threadIdx.x;             // 64 channels
    int n0 = blockIdx.x * 128;
    int n1 = n0 + 128; if (n1 > NN) n1 = NN;
    if (n0 >= NN) return;
    float acc = 0.f;
    int cur = batch[n0];
    for (int i = n0; i < n1; i++) {
        int b = batch[i];
        if (b != cur) { atomicAdd(&g_pooled[cur*CC + c], acc); acc = 0.f; cur = b; }
        acc += g_out2[(size_t)i * CC + c];
    }
    atomicAdd(&g_pooled[cur*CC + c], acc);
}

// ---------------- head MLP + log_softmax, one block of 64 per graph ----------------
__global__ void k_head(const float* __restrict__ w1, const float* __restrict__ b1v,
                       const float* __restrict__ w2, const float* __restrict__ b2v,
                       float* __restrict__ out) {
    __shared__ float p[64], zs[64], lg[KK];
    int b = blockIdx.x, t = threadIdx.x;
    p[t] = g_pooled[b*CC + t];
    __syncthreads();
    float z = b1v[t];
    #pragma unroll 16
    for (int k = 0; k < 64; k++) z += p[k] * w1[k*64 + t];
    z = z > 0.f ? z : expm1f(z);
    zs[t] = z;
    __syncthreads();
    if (t < KK) {
        float l = b2v[t];
        #pragma unroll 16
        for (int k = 0; k < 64; k++) l += zs[k] * w2[k*KK + t];
        lg[t] = l;
    }
    __syncthreads();
    if (t < KK) {
        float m = -1e30f;
        #pragma unroll
        for (int k = 0; k < KK; k++) m = fmaxf(m, lg[k]);
        float s = 0.f;
        #pragma unroll
        for (int k = 0; k < KK; k++) s += expf(lg[k] - m);
        out[b*KK + t] = lg[t] - m - logf(s);
    }
}

// ---------------- launch ----------------
extern "C" void kernel_launch(void* const* d_in, const int* in_sizes, int n_in,
                              void* d_out, int out_size) {
    const float* x        = (const float*)d_in[0];
    const int*   ei       = (const int*)  d_in[1];
    const int*   batch    = (const int*)  d_in[2];
    const float* W1       = (const float*)d_in[3];
    const float* att_src1 = (const float*)d_in[4];
    const float* att_dst1 = (const float*)d_in[5];
    const float* b1       = (const float*)d_in[6];
    const float* W2       = (const float*)d_in[7];
    const float* att_src2 = (const float*)d_in[8];
    const float* att_dst2 = (const float*)d_in[9];
    const float* b2       = (const float*)d_in[10];
    const float* l1w      = (const float*)d_in[11];
    const float* l1b      = (const float*)d_in[12];
    const float* l2w      = (const float*)d_in[13];
    const float* l2b      = (const float*)d_in[14];
    float* out = (float*)d_out;

    const int* src = ei;
    const int* dst = ei + EE;

    void *p_h1, *p_out1, *p_h2, *p_out2, *p_as1, *p_ad1, *p_as2, *p_ad2;
    cudaGetSymbolAddress(&p_h1,  g_h1);
    cudaGetSymbolAddress(&p_out1, g_out1);
    cudaGetSymbolAddress(&p_h2,  g_h2);
    cudaGetSymbolAddress(&p_out2, g_out2);
    cudaGetSymbolAddress(&p_as1, g_as1);
    cudaGetSymbolAddress(&p_ad1, g_ad1);
    cudaGetSymbolAddress(&p_as2, g_as2);
    cudaGetSymbolAddress(&p_ad2, g_ad2);
    float* h1   = (float*)p_h1;
    float* out1 = (float*)p_out1;
    float* h2   = (float*)p_h2;
    float* out2 = (float*)p_out2;
    float* as1  = (float*)p_as1;
    float* ad1  = (float*)p_ad1;
    float* as2  = (float*)p_as2;
    float* ad2  = (float*)p_ad2;

    // CSR build (by destination)
    k_init<<<(NN + 255)/256, 256>>>();
    k_count<<<(EE + 255)/256, 256>>>(dst);
    k_scan<<<1, 1024>>>();
    k_scatter<<<(ETOT + 255)/256, 256>>>(src, dst);

    // Layer 1: h1 = x @ W1  [50000,128]@[128,512]
    k_sgemm_t<128,128,16,8,8><<<dim3(HC/128, (NN + 127)/128), 256>>>(x, W1, h1, NN, HC, FF);
    k_attn<<<(NN*HH + 7)/8, 256>>>(h1, att_src1, att_dst1, as1, ad1, HH, NN*HH);
    k_agg <<<(NN*HH + 7)/8, 256>>>(h1, as1, ad1, b1, out1, HH, NN*HH);

    // Layer 2: h2 = out1 @ W2  [50000,512]@[512,64]
    k_sgemm_t<128,64,16,8,4><<<dim3(CC/64, (NN + 127)/128), 256>>>(out1, W2, h2, NN, CC, HC);
    k_attn<<<(NN + 7)/8, 256>>>(h2, att_src2, att_dst2, as2, ad2, 1, NN);
    k_agg <<<(NN + 7)/8, 256>>>(h2, as2, ad2, b2, out2, 1, NN);

    // Pool + head
    k_pool<<<(NN + 127)/128, 64>>>(batch);
    k_head<<<BB, 64>>>(l1w, l1b, l2w, l2b, out);
}